// round 4
// baseline (speedup 1.0000x reference)
#include <cuda_runtime.h>
#include <float.h>

// Problem constants (from reference)
#define B_      8
#define L_      2048
#define D_      256
#define T_      32
#define S_PARA  8
#define S_ADU   24
#define S_SHELL 24

#define D4      (D_ / 4)          // 64 float4 lanes per row
#define ROWS_TOPIC  (B_)                  // 8
#define ROWS_PARA   (B_ * S_PARA)         // 64
#define ROWS_SHELL  (B_ * S_SHELL)        // 192
#define ROWS_ADU    (B_ * S_ADU)         // 192

// flat output offsets (float elements), reference return order:
// (topic_out, para_reps, span_reps<-shell, adu_reps<-x)
#define OFF_TOPIC 0
#define OFF_PARA  (B_ * D_)                              // 2048
#define OFF_SHELL (OFF_PARA + B_ * S_PARA * D_)          // 18432
#define OFF_ADU   (OFF_SHELL + B_ * S_SHELL * D_)        // 67584

#define YS 4              // span-dimension split per block
#define CHUNK 64          // rows per para chunk
#define PARA_CHUNKS 4     // max para span = 256 rows -> 4 chunks

// block/slot layout (single kernel):
//   [0, 8)     topic rows             -> direct out
//   [8, 264)   para chunks (64 x 4)   -> scratch + last-block reduce
//   [264, 456) shell spans            -> direct out
//   [456, 648) adu (x) spans          -> direct out
#define SLOT_TOPIC 0
#define SLOT_PARA  (SLOT_TOPIC + ROWS_TOPIC)                 // 8
#define SLOT_SHELL (SLOT_PARA + ROWS_PARA * PARA_CHUNKS)     // 264
#define SLOT_ADU   (SLOT_SHELL + ROWS_SHELL)                 // 456
#define SLOTS_TOTAL (SLOT_ADU + ROWS_ADU)                    // 648

__device__ float g_partial[ROWS_PARA * PARA_CHUNKS * D_];   // 256 KB
__device__ int   g_count[ROWS_PARA];                        // zero-init; reset by last block

__device__ __forceinline__ float4 f4max(float4 a, float4 b) {
    float4 r;
    r.x = fmaxf(a.x, b.x);
    r.y = fmaxf(a.y, b.y);
    r.z = fmaxf(a.z, b.z);
    r.w = fmaxf(a.w, b.w);
    return r;
}

__device__ __forceinline__ float4 ldcg4(const float4* p) {
    float4 v;
    asm volatile("ld.global.cg.v4.f32 {%0,%1,%2,%3}, [%4];"
                 : "=f"(v.x), "=f"(v.y), "=f"(v.z), "=f"(v.w) : "l"(p));
    return v;
}

__global__ __launch_bounds__(64 * YS) void span_maxpool_fused_kernel(
    const float* __restrict__ topic_reps,   // [B,T,D]
    const float* __restrict__ word_reps,    // [B,L,D]
    const int*   __restrict__ para_spans,   // [B,S_PARA,3]
    const int*   __restrict__ x_spans,      // [B,S_ADU,3]
    const int*   __restrict__ shell_spans,  // [B,S_SHELL,3]
    float*       __restrict__ out)
{
    __shared__ float4 red[YS][D4];          // 4 KB
    __shared__ int s_last;

    const int slot = blockIdx.x;            // 0..647
    const int lane = threadIdx.x;           // 0..63
    const int ys   = threadIdx.y;           // 0..3

    const float4* src;      // first row of this block's chunk, at this lane
    int cnt;                // rows in this chunk (<=0 possible for empty para chunk)
    int para_i = -1;        // para span index if this is a para chunk
    int out_off = 0;        // direct-output offset for non-para slots

    if (slot < SLOT_PARA) {
        src = (const float4*)(topic_reps + (size_t)slot * T_ * D_) + lane;
        cnt = T_;
        out_off = OFF_TOPIC + slot * D_;
    } else if (slot < SLOT_SHELL) {
        const int k = slot - SLOT_PARA;
        para_i = k >> 2;                    // span index 0..63
        const int c = k & 3;                // chunk 0..3
        const int* sp = para_spans + para_i * 3;
        const int start = sp[1] + c * CHUNK;
        src = (const float4*)(word_reps + ((size_t)sp[0] * L_ + start) * D_) + lane;
        cnt = (sp[2] - sp[1] + 1) - c * CHUNK;
        if (cnt > CHUNK) cnt = CHUNK;
    } else if (slot < SLOT_ADU) {
        const int i = slot - SLOT_SHELL;
        const int* sp = shell_spans + i * 3;
        src = (const float4*)(word_reps + ((size_t)sp[0] * L_ + sp[1]) * D_) + lane;
        cnt = sp[2] - sp[1] + 1;
        out_off = OFF_SHELL + i * D_;
    } else {
        const int i = slot - SLOT_ADU;
        const int* sp = x_spans + i * 3;
        src = (const float4*)(word_reps + ((size_t)sp[0] * L_ + sp[1]) * D_) + lane;
        cnt = sp[2] - sp[1] + 1;
        out_off = OFF_ADU + i * D_;
    }

    float4 acc = make_float4(-FLT_MAX, -FLT_MAX, -FLT_MAX, -FLT_MAX);

    // y-slice ys pools rows ys, ys+YS, ... with 4x unroll (independent loads).
    int i = ys;
    for (; i + 3 * YS < cnt; i += 4 * YS) {
        float4 v0 = __ldg(src + (size_t)(i + 0 * YS) * D4);
        float4 v1 = __ldg(src + (size_t)(i + 1 * YS) * D4);
        float4 v2 = __ldg(src + (size_t)(i + 2 * YS) * D4);
        float4 v3 = __ldg(src + (size_t)(i + 3 * YS) * D4);
        acc = f4max(acc, f4max(f4max(v0, v1), f4max(v2, v3)));
    }
    for (; i < cnt; i += YS) {
        acc = f4max(acc, __ldg(src + (size_t)i * D4));
    }

    red[ys][lane] = acc;
    __syncthreads();

    if (para_i < 0) {
        // direct output
        if (ys == 0) {
            float4 r = f4max(f4max(red[0][lane], red[1][lane]),
                             f4max(red[2][lane], red[3][lane]));
            ((float4*)(out + out_off))[lane] = r;
        }
        return;
    }

    // ── para chunk: publish partial, last block reduces ──
    const int k = slot - SLOT_PARA;         // para chunk id 0..255
    if (ys == 0) {
        float4 r = f4max(f4max(red[0][lane], red[1][lane]),
                         f4max(red[2][lane], red[3][lane]));
        ((float4*)(g_partial + (size_t)k * D_))[lane] = r;
        __threadfence();                    // publish before arrival
    }
    __syncthreads();

    if (threadIdx.x == 0 && threadIdx.y == 0) {
        int old = atomicAdd(&g_count[para_i], 1);
        s_last = (old == PARA_CHUNKS - 1);
    }
    __syncthreads();

    if (s_last) {
        if (ys == 0) {
            const float4* base = (const float4*)(g_partial
                                 + (size_t)(para_i * PARA_CHUNKS) * D_) + lane;
            float4 a = ldcg4(base + 0 * D4);
            float4 b = ldcg4(base + 1 * D4);
            float4 c = ldcg4(base + 2 * D4);
            float4 d = ldcg4(base + 3 * D4);
            float4 r = f4max(f4max(a, b), f4max(c, d));
            ((float4*)(out + OFF_PARA + para_i * D_))[lane] = r;
        }
        if (threadIdx.x == 0 && threadIdx.y == 0) {
            g_count[para_i] = 0;            // reset for next graph replay
        }
    }
}

extern "C" void kernel_launch(void* const* d_in, const int* in_sizes, int n_in,
                              void* d_out, int out_size) {
    // metadata order: topic_reps, word_reps, topic_lens(int64, unused),
    //                 para_spans, x_spans, shell_spans
    const float* topic_reps  = (const float*)d_in[0];
    const float* word_reps   = (const float*)d_in[1];
    const int*   para_spans  = (const int*)d_in[3];
    const int*   x_spans     = (const int*)d_in[4];
    const int*   shell_spans = (const int*)d_in[5];
    float* out = (float*)d_out;

    dim3 block(64, YS);                // 256 threads
    span_maxpool_fused_kernel<<<SLOTS_TOTAL, block>>>(
        topic_reps, word_reps, para_spans, x_spans, shell_spans, out);
}

// round 5
// speedup vs baseline: 1.0332x; 1.0332x over previous
#include <cuda_runtime.h>
#include <float.h>

// Problem constants (from reference)
#define B_      8
#define L_      2048
#define D_      256
#define T_      32
#define S_PARA  8
#define S_ADU   24
#define S_SHELL 24

#define D4      (D_ / 4)          // 64 float4 lanes per row
#define ROWS_TOPIC  (B_)                  // 8
#define ROWS_PARA   (B_ * S_PARA)         // 64
#define ROWS_SHELL  (B_ * S_SHELL)        // 192
#define ROWS_ADU    (B_ * S_ADU)          // 192

// flat output offsets (float elements), reference return order:
// (topic_out, para_reps, span_reps<-shell, adu_reps<-x)
#define OFF_TOPIC 0
#define OFF_PARA  (B_ * D_)                              // 2048
#define OFF_SHELL (OFF_PARA + B_ * S_PARA * D_)          // 18432
#define OFF_ADU   (OFF_SHELL + B_ * S_SHELL * D_)        // 67584

#define YS 4              // span-dimension split within a block
#define CHUNK 32          // rows per chunk -> <=8 rows per ys-thread
#define PARA_CHUNKS 8     // max para span 256 rows
#define ADU_CHUNKS  2     // max adu span 64 rows

// block/slot layout (single kernel, 1096 blocks):
//   [0, 8)        topic rows (32 rows)         -> direct out
//   [8, 520)      para chunks (64 spans x 8)   -> scratch + last-block reduce
//   [520, 712)    shell spans (<=16 rows)      -> direct out
//   [712, 1096)   adu chunks (192 spans x 2)   -> scratch + last-block reduce
#define SLOT_TOPIC 0
#define SLOT_PARA  (SLOT_TOPIC + ROWS_TOPIC)                 // 8
#define SLOT_SHELL (SLOT_PARA + ROWS_PARA * PARA_CHUNKS)     // 520
#define SLOT_ADU   (SLOT_SHELL + ROWS_SHELL)                 // 712
#define SLOTS_TOTAL (SLOT_ADU + ROWS_ADU * ADU_CHUNKS)       // 1096

// scratch layout: para partials [0, 512), adu partials [512, 896)
#define PART_PARA 0
#define PART_ADU  (ROWS_PARA * PARA_CHUNKS)                  // 512
#define PART_TOTAL (PART_ADU + ROWS_ADU * ADU_CHUNKS)        // 896

// counters: para [0,64), adu [64, 256)
#define CNT_PARA 0
#define CNT_ADU  ROWS_PARA
#define CNT_TOTAL (ROWS_PARA + ROWS_ADU)

__device__ float g_partial[PART_TOTAL * D_];   // 896 KB static scratch
__device__ int   g_count[CNT_TOTAL];           // zero-init; reset by last block

__device__ __forceinline__ float4 f4max(float4 a, float4 b) {
    float4 r;
    r.x = fmaxf(a.x, b.x);
    r.y = fmaxf(a.y, b.y);
    r.z = fmaxf(a.z, b.z);
    r.w = fmaxf(a.w, b.w);
    return r;
}

__device__ __forceinline__ float4 ldcg4(const float4* p) {
    float4 v;
    asm volatile("ld.global.cg.v4.f32 {%0,%1,%2,%3}, [%4];"
                 : "=f"(v.x), "=f"(v.y), "=f"(v.z), "=f"(v.w) : "l"(p));
    return v;
}

__global__ __launch_bounds__(64 * YS) void span_maxpool_fused_kernel(
    const float* __restrict__ topic_reps,   // [B,T,D]
    const float* __restrict__ word_reps,    // [B,L,D]
    const int*   __restrict__ para_spans,   // [B,S_PARA,3]
    const int*   __restrict__ x_spans,      // [B,S_ADU,3]
    const int*   __restrict__ shell_spans,  // [B,S_SHELL,3]
    float*       __restrict__ out)
{
    __shared__ float4 red[YS][D4];          // 4 KB
    __shared__ int s_last;

    const int slot = blockIdx.x;            // 0..1095
    const int lane = threadIdx.x;           // 0..63
    const int ys   = threadIdx.y;           // 0..3

    const float4* src;      // first row of this block's chunk, at this lane
    int cnt;                // rows in this chunk (<=0 possible for empty chunk)
    int out_off = -1;       // direct-out offset (>=0 for single-chunk slots)
    int part_slot = -1;     // scratch partial slot (multi-chunk)
    int cnt_idx = -1;       // counter index
    int nchunks = 0;        // total chunks for this span
    int part_base = -1;     // first partial slot of this span
    int final_off = 0;      // output offset of this span (multi-chunk)

    if (slot < SLOT_PARA) {
        src = (const float4*)(topic_reps + (size_t)slot * T_ * D_) + lane;
        cnt = T_;
        out_off = OFF_TOPIC + slot * D_;
    } else if (slot < SLOT_SHELL) {
        const int k = slot - SLOT_PARA;     // 0..511
        const int i = k >> 3;               // para span 0..63
        const int c = k & 7;                // chunk 0..7
        const int* sp = para_spans + i * 3;
        const int start = sp[1] + c * CHUNK;
        src = (const float4*)(word_reps + ((size_t)sp[0] * L_ + start) * D_) + lane;
        cnt = (sp[2] - sp[1] + 1) - c * CHUNK;
        if (cnt > CHUNK) cnt = CHUNK;
        part_slot = PART_PARA + k;
        cnt_idx   = CNT_PARA + i;
        nchunks   = PARA_CHUNKS;
        part_base = PART_PARA + i * PARA_CHUNKS;
        final_off = OFF_PARA + i * D_;
    } else if (slot < SLOT_ADU) {
        const int i = slot - SLOT_SHELL;
        const int* sp = shell_spans + i * 3;
        src = (const float4*)(word_reps + ((size_t)sp[0] * L_ + sp[1]) * D_) + lane;
        cnt = sp[2] - sp[1] + 1;
        out_off = OFF_SHELL + i * D_;
    } else {
        const int k = slot - SLOT_ADU;      // 0..383
        const int i = k >> 1;               // adu span 0..191
        const int c = k & 1;                // chunk 0..1
        const int* sp = x_spans + i * 3;
        const int start = sp[1] + c * CHUNK;
        src = (const float4*)(word_reps + ((size_t)sp[0] * L_ + start) * D_) + lane;
        cnt = (sp[2] - sp[1] + 1) - c * CHUNK;
        if (cnt > CHUNK) cnt = CHUNK;
        part_slot = PART_ADU + k;
        cnt_idx   = CNT_ADU + i;
        nchunks   = ADU_CHUNKS;
        part_base = PART_ADU + i * ADU_CHUNKS;
        final_off = OFF_ADU + i * D_;
    }

    float4 acc = make_float4(-FLT_MAX, -FLT_MAX, -FLT_MAX, -FLT_MAX);

    // y-slice ys pools rows ys, ys+YS, ... ; 4x unroll (independent loads).
    int i = ys;
    for (; i + 3 * YS < cnt; i += 4 * YS) {
        float4 v0 = __ldg(src + (size_t)(i + 0 * YS) * D4);
        float4 v1 = __ldg(src + (size_t)(i + 1 * YS) * D4);
        float4 v2 = __ldg(src + (size_t)(i + 2 * YS) * D4);
        float4 v3 = __ldg(src + (size_t)(i + 3 * YS) * D4);
        acc = f4max(acc, f4max(f4max(v0, v1), f4max(v2, v3)));
    }
    for (; i < cnt; i += YS) {
        acc = f4max(acc, __ldg(src + (size_t)i * D4));
    }

    red[ys][lane] = acc;
    __syncthreads();

    if (out_off >= 0) {
        // single-chunk slot: direct output
        if (ys == 0) {
            float4 r = f4max(f4max(red[0][lane], red[1][lane]),
                             f4max(red[2][lane], red[3][lane]));
            ((float4*)(out + out_off))[lane] = r;
        }
        return;
    }

    // ── multi-chunk span: publish partial, last arriving block reduces ──
    if (ys == 0) {
        float4 r = f4max(f4max(red[0][lane], red[1][lane]),
                         f4max(red[2][lane], red[3][lane]));
        ((float4*)(g_partial + (size_t)part_slot * D_))[lane] = r;
        __threadfence();                    // publish before arrival
    }
    __syncthreads();

    if (threadIdx.x == 0 && threadIdx.y == 0) {
        int old = atomicAdd(&g_count[cnt_idx], 1);
        s_last = (old == nchunks - 1);
    }
    __syncthreads();

    if (s_last) {
        if (ys == 0) {
            const float4* base = (const float4*)(g_partial
                                 + (size_t)part_base * D_) + lane;
            float4 r = ldcg4(base);
            #pragma unroll 8
            for (int c = 1; c < nchunks; c++) {
                r = f4max(r, ldcg4(base + (size_t)c * D4));
            }
            ((float4*)(out + final_off))[lane] = r;
        }
        if (threadIdx.x == 0 && threadIdx.y == 0) {
            g_count[cnt_idx] = 0;           // reset for next graph replay
        }
    }
}

extern "C" void kernel_launch(void* const* d_in, const int* in_sizes, int n_in,
                              void* d_out, int out_size) {
    // metadata order: topic_reps, word_reps, topic_lens(int64, unused),
    //                 para_spans, x_spans, shell_spans
    const float* topic_reps  = (const float*)d_in[0];
    const float* word_reps   = (const float*)d_in[1];
    const int*   para_spans  = (const int*)d_in[3];
    const int*   x_spans     = (const int*)d_in[4];
    const int*   shell_spans = (const int*)d_in[5];
    float* out = (float*)d_out;

    dim3 block(64, YS);                // 256 threads
    span_maxpool_fused_kernel<<<SLOTS_TOTAL, block>>>(
        topic_reps, word_reps, para_spans, x_spans, shell_spans, out);
}